// round 7
// baseline (speedup 1.0000x reference)
#include <cuda_runtime.h>
#include <cstdint>

#define NN 8192
#define FF 64
#define RM 32                 // rows per CTA
#define KT 64                 // k-tile
#define NT (NN / KT)          // 128 tiles
#define SA 68                 // smem row stride (floats)

// smem layout (floats):
//  As0 [32*SA] @ 0        As1 [32*SA] @ 32*SA
//  Bs0 [64*SA] @ 64*SA    Bs1 [64*SA] @ 128*SA
//  rs  [128]   @ 192*SA
// epilogue aliases: Nsm=As0, Fsm=As1, Ws[128*SA]=Bs0..Bs1 (contiguous)
#define SMEM_FLOATS (192 * SA + 128)
#define SMEM_BYTES  (SMEM_FLOATS * 4)

// feat transposed to [n][k], tf32-rounded bit patterns
__device__ uint32_t g_featT[FF * NN];

static __device__ __forceinline__ uint32_t tf32b(float x) {
    uint32_t r; asm("cvt.rna.tf32.f32 %0, %1;" : "=r"(r) : "f"(x)); return r;
}
static __device__ __forceinline__ uint32_t s2u(const void* p) {
    uint32_t a;
    asm("{ .reg .u64 t; cvta.to.shared.u64 t, %1; cvt.u32.u64 %0, t; }" : "=r"(a) : "l"(p));
    return a;
}
static __device__ __forceinline__ void ldsm4(uint32_t* f, uint32_t addr) {
    asm volatile("ldmatrix.sync.aligned.m8n8.x4.shared.b16 {%0,%1,%2,%3}, [%4];"
                 : "=r"(f[0]), "=r"(f[1]), "=r"(f[2]), "=r"(f[3]) : "r"(addr));
}
static __device__ __forceinline__ void mma_tf32(float* c, const uint32_t* a,
                                                uint32_t b0, uint32_t b1) {
    asm volatile(
        "mma.sync.aligned.m16n8k8.row.col.f32.tf32.tf32.f32 "
        "{%0,%1,%2,%3}, {%4,%5,%6,%7}, {%8,%9}, {%0,%1,%2,%3};"
        : "+f"(c[0]), "+f"(c[1]), "+f"(c[2]), "+f"(c[3])
        : "r"(a[0]), "r"(a[1]), "r"(a[2]), "r"(a[3]), "r"(b0), "r"(b1));
}

// ---- prep: featT[n][k] = tf32(feat[k][n]) via smem tile transpose ----
__global__ __launch_bounds__(256)
void prep_featT(const float* __restrict__ feat)
{
    __shared__ float t[64][65];
    const int k0 = blockIdx.x * 64;
    const int tid = threadIdx.x;
    const int r = tid >> 2, q = tid & 3;

    const float* fp = feat + (size_t)(k0 + r) * FF + 16 * q;
    #pragma unroll
    for (int j = 0; j < 4; j++) {
        float4 v = *(const float4*)(fp + 4 * j);
        t[r][16 * q + 4 * j + 0] = v.x;
        t[r][16 * q + 4 * j + 1] = v.y;
        t[r][16 * q + 4 * j + 2] = v.z;
        t[r][16 * q + 4 * j + 3] = v.w;
    }
    __syncthreads();

    uint32_t* dst = g_featT + (size_t)r * NN + k0 + 16 * q;
    #pragma unroll
    for (int j = 0; j < 4; j++) {
        uint4 c;
        c.x = tf32b(t[16 * q + 4 * j + 0][r]);
        c.y = tf32b(t[16 * q + 4 * j + 1][r]);
        c.z = tf32b(t[16 * q + 4 * j + 2][r]);
        c.w = tf32b(t[16 * q + 4 * j + 3][r]);
        *(uint4*)(dst + 4 * j) = c;
    }
}

// ---- main fused kernel: 128 threads, 4 warps, warp tile 16x32, double-buffered ----
__global__ __launch_bounds__(128, 2)
void sage_mma_kernel(const float* __restrict__ adj,
                     const float* __restrict__ feat,
                     const float* __restrict__ W,
                     float* __restrict__ out)
{
    extern __shared__ float sm[];
    float* As0 = sm;                   // A buffers: 32*SA each
    float* Bs0 = sm + 64 * SA;         // B buffers: 64*SA each
    float* rs  = sm + 192 * SA;        // 128 rowsum partials
    float* Nsm = sm;                   // epilogue: neigh  (alias As0)
    float* Fsm = sm + 32 * SA;         // epilogue: feat   (alias As1)
    float* Ws  = sm + 64 * SA;         // epilogue: W^T [128][SA] (alias Bs0+Bs1)

    const int tid  = threadIdx.x;
    const int lane = tid & 31, warp = tid >> 5;
    const int wm = warp >> 1, wn = warp & 1;      // warp tile: rows 16*wm, cols 32*wn
    const int row0 = blockIdx.x * RM;

    // loader mappings
    const int rA = tid >> 2, qA = tid & 3;        // A: row rA (0..31), 16 floats at 16*qA
    const int rB = tid >> 1, hB = tid & 1;        // B: n-row rB (0..63), 32 floats at 32*hB

    const float*    aP = adj + (size_t)(row0 + rA) * NN + 16 * qA;
    const uint32_t* bP = g_featT + (size_t)rB * NN + 32 * hB;

    // ldmatrix base addresses (buffer 0)
    const int mi = lane >> 3, ri = lane & 7;
    const uint32_t aAddr0 = s2u(&As0[(16 * wm + (mi & 1) * 8 + ri) * SA + (mi >> 1) * 4]);
    const uint32_t bAddrA = s2u(&Bs0[(32 * wn + (mi >> 1) * 8 + ri) * SA + (mi & 1) * 4]);
    const uint32_t bAddrB = s2u(&Bs0[(32 * wn + 16 + (mi >> 1) * 8 + ri) * SA + (mi & 1) * 4]);
    const uint32_t ABUF = 32 * SA * 4;            // byte offset buf0 -> buf1 (A)
    const uint32_t BBUF = 64 * SA * 4;            // byte offset buf0 -> buf1 (B)

    float acc[4][4] = {};
    float rsum = 0.0f;

    float4 ra[4]; uint4 rb[8];
    // stage tile 0
    #pragma unroll
    for (int j = 0; j < 4; j++) ra[j] = *(const float4*)(aP + 4 * j);
    #pragma unroll
    for (int j = 0; j < 8; j++) rb[j] = *(const uint4*)(bP + 4 * j);

    // STS tile 0 -> buf 0
    #pragma unroll
    for (int j = 0; j < 4; j++) {
        float4 v = ra[j];
        rsum += (v.x + v.y) + (v.z + v.w);
        uint4 c; c.x = tf32b(v.x); c.y = tf32b(v.y); c.z = tf32b(v.z); c.w = tf32b(v.w);
        *(uint4*)&As0[rA * SA + 16 * qA + 4 * j] = c;
    }
    #pragma unroll
    for (int j = 0; j < 8; j++)
        *(uint4*)&Bs0[rB * SA + 32 * hB + 4 * j] = rb[j];

    // LDG tile 1
    #pragma unroll
    for (int j = 0; j < 4; j++) ra[j] = *(const float4*)(aP + KT + 4 * j);
    #pragma unroll
    for (int j = 0; j < 8; j++) rb[j] = *(const uint4*)(bP + KT + 4 * j);

    __syncthreads();

    for (int t = 0; t < NT; t++) {
        const uint32_t aA = aAddr0 + (t & 1) * ABUF;
        const uint32_t bA = bAddrA + (t & 1) * BBUF;
        const uint32_t bB = bAddrB + (t & 1) * BBUF;

        // ---- MMA phase on buf (t&1), fragment-pipelined over 8 k-steps ----
        uint32_t af[2][4], b0f[2][4], b1f[2][4];
        ldsm4(af[0], aA); ldsm4(b0f[0], bA); ldsm4(b1f[0], bB);
        #pragma unroll
        for (int ks = 0; ks < 8; ks++) {
            const int cur = ks & 1, nxt = cur ^ 1;
            if (ks < 7) {
                ldsm4(af[nxt],  aA + (ks + 1) * 32);
                ldsm4(b0f[nxt], bA + (ks + 1) * 32);
                ldsm4(b1f[nxt], bB + (ks + 1) * 32);
            }
            mma_tf32(acc[0], af[cur], b0f[cur][0], b0f[cur][1]);
            mma_tf32(acc[1], af[cur], b0f[cur][2], b0f[cur][3]);
            mma_tf32(acc[2], af[cur], b1f[cur][0], b1f[cur][1]);
            mma_tf32(acc[3], af[cur], b1f[cur][2], b1f[cur][3]);
        }

        // ---- STS tile t+1 into the other buffer; LDG tile t+2 ----
        if (t + 1 < NT) {
            float* Ad = As0 + ((t + 1) & 1) * 32 * SA;
            float* Bd = Bs0 + ((t + 1) & 1) * 64 * SA;
            #pragma unroll
            for (int j = 0; j < 4; j++) {
                float4 v = ra[j];
                rsum += (v.x + v.y) + (v.z + v.w);
                uint4 c; c.x = tf32b(v.x); c.y = tf32b(v.y); c.z = tf32b(v.z); c.w = tf32b(v.w);
                *(uint4*)&Ad[rA * SA + 16 * qA + 4 * j] = c;
            }
            #pragma unroll
            for (int j = 0; j < 8; j++)
                *(uint4*)&Bd[rB * SA + 32 * hB + 4 * j] = rb[j];

            if (t + 2 < NT) {
                const float*    ap = aP + (size_t)(t + 2) * KT;
                const uint32_t* bp = bP + (t + 2) * KT;
                #pragma unroll
                for (int j = 0; j < 4; j++) ra[j] = *(const float4*)(ap + 4 * j);
                #pragma unroll
                for (int j = 0; j < 8; j++) rb[j] = *(const uint4*)(bp + 4 * j);
            }
        }
        __syncthreads();
    }

    // ---- rowsum reduce (rs[tid] == rs[rA*4+qA]) ----
    rs[tid] = rsum;
    __syncthreads();

    // ---- epilogue staging: neigh/deg -> Nsm, feat -> Fsm, W^T -> Ws ----
    {
        const int g = lane >> 2, t2 = lane & 3;
        const int rowa = 16 * wm + g, rowb = rowa + 8;
        float inva = 1.0f / (rs[4 * rowa] + rs[4 * rowa + 1] +
                             rs[4 * rowa + 2] + rs[4 * rowa + 3] + 1.0f);
        float invb = 1.0f / (rs[4 * rowb] + rs[4 * rowb + 1] +
                             rs[4 * rowb + 2] + rs[4 * rowb + 3] + 1.0f);
        #pragma unroll
        for (int nb = 0; nb < 4; nb++) {
            const int col = 32 * wn + 8 * nb + 2 * t2;
            Nsm[rowa * SA + col]     = acc[nb][0] * inva;
            Nsm[rowa * SA + col + 1] = acc[nb][1] * inva;
            Nsm[rowb * SA + col]     = acc[nb][2] * invb;
            Nsm[rowb * SA + col + 1] = acc[nb][3] * invb;
        }
    }
    {
        const float* fp = feat + (size_t)(row0 + rA) * FF + 16 * qA;
        #pragma unroll
        for (int j = 0; j < 4; j++)
            *(float4*)&Fsm[rA * SA + 16 * qA + 4 * j] = *(const float4*)(fp + 4 * j);

        // W: [64 out][128 k] -> Ws[k][o]; thread: o = tid>>1, k half = tid&1
        const int o = tid >> 1, kh = tid & 1;
        const float* wp = W + (size_t)o * 128 + 64 * kh;
        #pragma unroll
        for (int j = 0; j < 64; j++)
            Ws[(64 * kh + j) * SA + o] = wp[j];
    }
    __syncthreads();

    // ---- exact fp32 epilogue GEMM: out[r][o] = feat.W1^T + neigh.W2^T ----
    float acc2[16] = {};
    #pragma unroll 4
    for (int k = 0; k < 64; k++) {
        float af = Fsm[rA * SA + k];
        float an = Nsm[rA * SA + k];
        #pragma unroll
        for (int j = 0; j < 4; j++) {
            float4 w1 = *(float4*)&Ws[k * SA + 16 * qA + 4 * j];
            float4 w2 = *(float4*)&Ws[(64 + k) * SA + 16 * qA + 4 * j];
            acc2[4 * j + 0] = fmaf(af, w1.x, fmaf(an, w2.x, acc2[4 * j + 0]));
            acc2[4 * j + 1] = fmaf(af, w1.y, fmaf(an, w2.y, acc2[4 * j + 1]));
            acc2[4 * j + 2] = fmaf(af, w1.z, fmaf(an, w2.z, acc2[4 * j + 2]));
            acc2[4 * j + 3] = fmaf(af, w1.w, fmaf(an, w2.w, acc2[4 * j + 3]));
        }
    }

    float* op = out + (size_t)(row0 + rA) * FF + 16 * qA;
    #pragma unroll
    for (int j = 0; j < 4; j++) {
        float4 v = make_float4(acc2[4 * j + 0], acc2[4 * j + 1],
                               acc2[4 * j + 2], acc2[4 * j + 3]);
        *(float4*)(op + 4 * j) = v;
    }
}

extern "C" void kernel_launch(void* const* d_in, const int* in_sizes, int n_in,
                              void* d_out, int out_size)
{
    const float* adj  = (const float*)d_in[0];   // [8192, 8192]
    const float* feat = (const float*)d_in[1];   // [8192, 64]
    const float* W    = (const float*)d_in[2];   // [64, 128]
    float* out        = (float*)d_out;           // [8192, 64]

    cudaFuncSetAttribute(sage_mma_kernel,
                         cudaFuncAttributeMaxDynamicSharedMemorySize, SMEM_BYTES);
    prep_featT<<<NN / 64, 256>>>(feat);
    sage_mma_kernel<<<NN / RM, 128, SMEM_BYTES>>>(adj, feat, W, out);
}

// round 10
// speedup vs baseline: 1.7386x; 1.7386x over previous
#include <cuda_runtime.h>
#include <cstdint>

#define NN 8192
#define FF 64
#define RM 128                 // rows per CTA
#define KT 64                  // k-tile
#define KSPLIT 4
#define KRANGE (NN / KSPLIT)   // 2048
#define NT (KRANGE / KT)       // 32 tiles per CTA
#define SA 68                  // smem row stride (floats)

// As[128*SA] + Bs[64*SA] + rs[256]
#define SMEM_FLOATS (128 * SA + 64 * SA + 256)
#define SMEM_BYTES  (SMEM_FLOATS * 4)

__device__ uint32_t g_featT[FF * NN];        // feat^T, tf32 bits   (2MB)
__device__ float    g_pn[KSPLIT][NN][FF];    // partial neigh sums  (8MB)
__device__ float    g_rs[KSPLIT][NN];        // partial rowsums

static __device__ __forceinline__ uint32_t tf32b(float x) {
    uint32_t r; asm("cvt.rna.tf32.f32 %0, %1;" : "=r"(r) : "f"(x)); return r;
}
static __device__ __forceinline__ uint32_t s2u(const void* p) {
    uint32_t a;
    asm("{ .reg .u64 t; cvta.to.shared.u64 t, %1; cvt.u32.u64 %0, t; }" : "=r"(a) : "l"(p));
    return a;
}
static __device__ __forceinline__ void ldsm4(uint32_t* f, uint32_t addr) {
    asm volatile("ldmatrix.sync.aligned.m8n8.x4.shared.b16 {%0,%1,%2,%3}, [%4];"
                 : "=r"(f[0]), "=r"(f[1]), "=r"(f[2]), "=r"(f[3]) : "r"(addr));
}
static __device__ __forceinline__ void mma_tf32(float* c, const uint32_t* a,
                                                uint32_t b0, uint32_t b1) {
    asm volatile(
        "mma.sync.aligned.m16n8k8.row.col.f32.tf32.tf32.f32 "
        "{%0,%1,%2,%3}, {%4,%5,%6,%7}, {%8,%9}, {%0,%1,%2,%3};"
        : "+f"(c[0]), "+f"(c[1]), "+f"(c[2]), "+f"(c[3])
        : "r"(a[0]), "r"(a[1]), "r"(a[2]), "r"(a[3]), "r"(b0), "r"(b1));
}

// ---- prep: featT[n][k] = tf32(feat[k][n]) ----
__global__ __launch_bounds__(256)
void prep_featT(const float* __restrict__ feat)
{
    __shared__ float t[64][65];
    const int k0 = blockIdx.x * 64;
    const int tid = threadIdx.x;
    const int r = tid >> 2, q = tid & 3;

    const float* fp = feat + (size_t)(k0 + r) * FF + 16 * q;
    #pragma unroll
    for (int j = 0; j < 4; j++) {
        float4 v = *(const float4*)(fp + 4 * j);
        t[r][16 * q + 4 * j + 0] = v.x;
        t[r][16 * q + 4 * j + 1] = v.y;
        t[r][16 * q + 4 * j + 2] = v.z;
        t[r][16 * q + 4 * j + 3] = v.w;
    }
    __syncthreads();

    uint32_t* dst = g_featT + (size_t)r * NN + k0 + 16 * q;
    #pragma unroll
    for (int j = 0; j < 4; j++) {
        uint4 c;
        c.x = tf32b(t[16 * q + 4 * j + 0][r]);
        c.y = tf32b(t[16 * q + 4 * j + 1][r]);
        c.z = tf32b(t[16 * q + 4 * j + 2][r]);
        c.w = tf32b(t[16 * q + 4 * j + 3][r]);
        *(uint4*)(dst + 4 * j) = c;
    }
}

// ---- main kernel: 128x64 CTA tile, 8 warps (warp tile 32x32), K-split x4 ----
__global__ __launch_bounds__(256, 2)
void sage_mma_kernel(const float* __restrict__ adj)
{
    extern __shared__ float sm[];
    float* As = sm;                 // [128][SA]
    float* Bs = sm + 128 * SA;      // [64][SA]
    float* rs = sm + 192 * SA;      // [256]

    const int tid  = threadIdx.x;
    const int lane = tid & 31, warp = tid >> 5;
    const int wm = warp >> 1, wn = warp & 1;   // warp tile: rows 32*wm, cols 32*wn
    const int rb   = blockIdx.x >> 2;
    const int kspl = blockIdx.x & 3;
    const int row0 = rb * RM;
    const int kbase = kspl * KRANGE;

    // loader mappings
    const int rA = tid >> 1, hA = tid & 1;     // A: row rA (0..127), 32 floats at 32*hA
    const int rB = tid >> 2, qB = tid & 3;     // B: n-row rB (0..63), 16 floats at 16*qB

    const float*    aP = adj + (size_t)(row0 + rA) * NN + kbase + 32 * hA;
    const uint32_t* bP = g_featT + (size_t)rB * NN + kbase + 16 * qB;

    // ldmatrix base addresses
    const int mi = lane >> 3, ri = lane & 7;
    const uint32_t aAddr0 = s2u(&As[(32 * wm + (mi & 1) * 8 + ri) * SA + (mi >> 1) * 4]);
    const uint32_t aAddr1 = aAddr0 + 16 * SA * 4;
    const uint32_t bAddr0 = s2u(&Bs[(32 * wn + (mi >> 1) * 8 + ri) * SA + (mi & 1) * 4]);
    const uint32_t bAddr1 = bAddr0 + 16 * SA * 4;

    float acc[2][4][4] = {};
    float rsum = 0.0f;

    float4 ra[8]; uint4 rbuf[4];
    #pragma unroll
    for (int j = 0; j < 8; j++) ra[j] = *(const float4*)(aP + 4 * j);
    #pragma unroll
    for (int j = 0; j < 4; j++) rbuf[j] = *(const uint4*)(bP + 4 * j);

    for (int t = 0; t < NT; t++) {
        // ---- STS staged tile (rowsum from raw fp32; store tf32 bits) ----
        #pragma unroll
        for (int j = 0; j < 8; j++) {
            float4 v = ra[j];
            rsum += (v.x + v.y) + (v.z + v.w);
            uint4 c; c.x = tf32b(v.x); c.y = tf32b(v.y); c.z = tf32b(v.z); c.w = tf32b(v.w);
            *(uint4*)&As[rA * SA + 32 * hA + 4 * j] = c;
        }
        #pragma unroll
        for (int j = 0; j < 4; j++)
            *(uint4*)&Bs[rB * SA + 16 * qB + 4 * j] = rbuf[j];
        __syncthreads();

        // ---- prefetch next tile (overlaps MMA phase) ----
        if (t + 1 < NT) {
            const float*    ap = aP + (size_t)(t + 1) * KT;
            const uint32_t* bp = bP + (t + 1) * KT;
            #pragma unroll
            for (int j = 0; j < 8; j++) ra[j] = *(const float4*)(ap + 4 * j);
            #pragma unroll
            for (int j = 0; j < 4; j++) rbuf[j] = *(const uint4*)(bp + 4 * j);
        }

        // ---- MMA phase: 8 k-steps, warp tile 32x32 ----
        #pragma unroll
        for (int ks = 0; ks < 8; ks++) {
            uint32_t a0[4], a1[4], b0[4], b1[4];
            ldsm4(a0, aAddr0 + ks * 32);
            ldsm4(a1, aAddr1 + ks * 32);
            ldsm4(b0, bAddr0 + ks * 32);
            ldsm4(b1, bAddr1 + ks * 32);
            mma_tf32(acc[0][0], a0, b0[0], b0[1]);
            mma_tf32(acc[0][1], a0, b0[2], b0[3]);
            mma_tf32(acc[0][2], a0, b1[0], b1[1]);
            mma_tf32(acc[0][3], a0, b1[2], b1[3]);
            mma_tf32(acc[1][0], a1, b0[0], b0[1]);
            mma_tf32(acc[1][1], a1, b0[2], b0[3]);
            mma_tf32(acc[1][2], a1, b1[0], b1[1]);
            mma_tf32(acc[1][3], a1, b1[2], b1[3]);
        }
        __syncthreads();
    }

    // ---- partial rowsums: rA = tid>>1, so threads 2r,2r+1 cover row r ----
    rs[tid] = rsum;
    __syncthreads();
    if (tid < 128)
        g_rs[kspl][row0 + tid] = rs[2 * tid] + rs[2 * tid + 1];

    // ---- partial neigh sums -> g_pn[kspl] ----
    {
        const int g = lane >> 2, c2 = 2 * (lane & 3);
        float* pb = &g_pn[kspl][row0][0];
        #pragma unroll
        for (int ab = 0; ab < 2; ab++) {
            #pragma unroll
            for (int nb = 0; nb < 4; nb++) {
                const int rr = 32 * wm + 16 * ab + g;
                const int cc = 32 * wn + 8 * nb + c2;
                float2 lo = make_float2(acc[ab][nb][0], acc[ab][nb][1]);
                float2 hi = make_float2(acc[ab][nb][2], acc[ab][nb][3]);
                *(float2*)(pb + (size_t)rr * FF + cc)       = lo;
                *(float2*)(pb + (size_t)(rr + 8) * FF + cc) = hi;
            }
        }
    }
}

// ---- combine: out = feat@W1^T + ((sum_s pn_s)/deg)@W2^T   (exact fp32) ----
__global__ __launch_bounds__(256)
void combine_kernel(const float* __restrict__ feat,
                    const float* __restrict__ W,
                    float* __restrict__ out)
{
    __shared__ float WsmT[128][SA];   // [k][o]

    const int tid = threadIdx.x;
    const int r = blockIdx.x * 64 + (tid >> 2);
    const int q = tid & 3;            // outputs 16q..16q+15

    // stage W transposed: WsmT[k][o] = W[o][k]
    {
        const int o = tid >> 2, kq = tid & 3;
        const float* wp = W + (size_t)o * 128 + 32 * kq;
        #pragma unroll
        for (int j = 0; j < 32; j++)
            WsmT[32 * kq + j][o] = wp[j];
    }
    __syncthreads();

    const float inv = 1.0f / (g_rs[0][r] + g_rs[1][r] + g_rs[2][r] + g_rs[3][r] + 1.0f);

    const float4* f4 = (const float4*)(feat + (size_t)r * FF);
    const float4* p0 = (const float4*)&g_pn[0][r][0];
    const float4* p1 = (const float4*)&g_pn[1][r][0];
    const float4* p2 = (const float4*)&g_pn[2][r][0];
    const float4* p3 = (const float4*)&g_pn[3][r][0];

    float acc[16] = {};
    #pragma unroll 4
    for (int k4 = 0; k4 < 16; k4++) {
        float4 f = f4[k4];
        float4 s0 = p0[k4], s1 = p1[k4], s2 = p2[k4], s3 = p3[k4];
        float4 an4;
        an4.x = (s0.x + s1.x + s2.x + s3.x) * inv;
        an4.y = (s0.y + s1.y + s2.y + s3.y) * inv;
        an4.z = (s0.z + s1.z + s2.z + s3.z) * inv;
        an4.w = (s0.w + s1.w + s2.w + s3.w) * inv;
        const float af[4] = {f.x, f.y, f.z, f.w};
        const float an[4] = {an4.x, an4.y, an4.z, an4.w};
        #pragma unroll
        for (int e = 0; e < 4; e++) {
            const int k = 4 * k4 + e;
            #pragma unroll
            for (int i = 0; i < 4; i++) {
                float4 w1 = *(const float4*)&WsmT[k][16 * q + 4 * i];
                float4 w2 = *(const float4*)&WsmT[64 + k][16 * q + 4 * i];
                acc[4 * i + 0] = fmaf(af[e], w1.x, fmaf(an[e], w2.x, acc[4 * i + 0]));
                acc[4 * i + 1] = fmaf(af[e], w1.y, fmaf(an[e], w2.y, acc[4 * i + 1]));
                acc[4 * i + 2] = fmaf(af[e], w1.z, fmaf(an[e], w2.z, acc[4 * i + 2]));
                acc[4 * i + 3] = fmaf(af[e], w1.w, fmaf(an[e], w2.w, acc[4 * i + 3]));
            }
        }
    }

    float* op = out + (size_t)r * FF + 16 * q;
    #pragma unroll
    for (int i = 0; i < 4; i++)
        *(float4*)(op + 4 * i) = make_float4(acc[4 * i + 0], acc[4 * i + 1],
                                             acc[4 * i + 2], acc[4 * i + 3]);
}

extern "C" void kernel_launch(void* const* d_in, const int* in_sizes, int n_in,
                              void* d_out, int out_size)
{
    const float* adj  = (const float*)d_in[0];   // [8192, 8192]
    const float* feat = (const float*)d_in[1];   // [8192, 64]
    const float* W    = (const float*)d_in[2];   // [64, 128]
    float* out        = (float*)d_out;           // [8192, 64]

    cudaFuncSetAttribute(sage_mma_kernel,
                         cudaFuncAttributeMaxDynamicSharedMemorySize, SMEM_BYTES);
    prep_featT<<<NN / 64, 256>>>(feat);
    sage_mma_kernel<<<(NN / RM) * KSPLIT, 256, SMEM_BYTES>>>(adj);
    combine_kernel<<<NN / 64, 256>>>(feat, W, out);
}

// round 11
// speedup vs baseline: 1.9523x; 1.1229x over previous
#include <cuda_runtime.h>
#include <cstdint>

#define NN 8192
#define FF 64
#define RM 128                 // rows per CTA
#define KT 64                  // k-tile
#define KSPLIT 4
#define KRANGE (NN / KSPLIT)   // 2048
#define NT (KRANGE / KT)       // 32 tiles per CTA
#define SA 68                  // smem row stride (floats)
#define STG (192 * SA)         // floats per stage (A 128*SA + B 64*SA)

#define SMEM_BYTES (2 * STG * 4)   // 104448 B -> 2 CTAs/SM

__device__ uint32_t g_featT[FF * NN];        // feat^T, tf32-RN bits (2MB)
__device__ float    g_pn[KSPLIT][NN][FF];    // partial neigh sums   (8MB)
__device__ float    g_rs[KSPLIT][NN];        // partial rowsums

static __device__ __forceinline__ uint32_t tf32b(float x) {
    uint32_t r; asm("cvt.rna.tf32.f32 %0, %1;" : "=r"(r) : "f"(x)); return r;
}
static __device__ __forceinline__ uint32_t s2u(const void* p) {
    uint32_t a;
    asm("{ .reg .u64 t; cvta.to.shared.u64 t, %1; cvt.u32.u64 %0, t; }" : "=r"(a) : "l"(p));
    return a;
}
static __device__ __forceinline__ void cpasync16(uint32_t dst, const void* src) {
    asm volatile("cp.async.cg.shared.global [%0], [%1], 16;"
                 :: "r"(dst), "l"(src) : "memory");
}
static __device__ __forceinline__ void cp_commit() {
    asm volatile("cp.async.commit_group;" ::: "memory");
}
static __device__ __forceinline__ void cp_wait1() {
    asm volatile("cp.async.wait_group 1;" ::: "memory");
}
static __device__ __forceinline__ void ldsm4(uint32_t* f, uint32_t addr) {
    asm volatile("ldmatrix.sync.aligned.m8n8.x4.shared.b16 {%0,%1,%2,%3}, [%4];"
                 : "=r"(f[0]), "=r"(f[1]), "=r"(f[2]), "=r"(f[3]) : "r"(addr));
}
static __device__ __forceinline__ void mma_tf32(float* c, const uint32_t* a,
                                                uint32_t b0, uint32_t b1) {
    asm volatile(
        "mma.sync.aligned.m16n8k8.row.col.f32.tf32.tf32.f32 "
        "{%0,%1,%2,%3}, {%4,%5,%6,%7}, {%8,%9}, {%0,%1,%2,%3};"
        : "+f"(c[0]), "+f"(c[1]), "+f"(c[2]), "+f"(c[3])
        : "r"(a[0]), "r"(a[1]), "r"(a[2]), "r"(a[3]), "r"(b0), "r"(b1));
}

// ---- prep: featT[n][k] = tf32_rn(feat[k][n]) ----
__global__ __launch_bounds__(256)
void prep_featT(const float* __restrict__ feat)
{
    __shared__ float t[64][65];
    const int k0 = blockIdx.x * 64;
    const int tid = threadIdx.x;
    const int r = tid >> 2, q = tid & 3;

    const float* fp = feat + (size_t)(k0 + r) * FF + 16 * q;
    #pragma unroll
    for (int j = 0; j < 4; j++) {
        float4 v = *(const float4*)(fp + 4 * j);
        t[r][16 * q + 4 * j + 0] = v.x;
        t[r][16 * q + 4 * j + 1] = v.y;
        t[r][16 * q + 4 * j + 2] = v.z;
        t[r][16 * q + 4 * j + 3] = v.w;
    }
    __syncthreads();

    uint32_t* dst = g_featT + (size_t)r * NN + k0 + 16 * q;
    #pragma unroll
    for (int j = 0; j < 4; j++) {
        uint4 c;
        c.x = tf32b(t[16 * q + 4 * j + 0][r]);
        c.y = tf32b(t[16 * q + 4 * j + 1][r]);
        c.z = tf32b(t[16 * q + 4 * j + 2][r]);
        c.w = tf32b(t[16 * q + 4 * j + 3][r]);
        *(uint4*)(dst + 4 * j) = c;
    }
}

// ---- main kernel: cp.async 2-stage pipeline, rowsum via ones-MMA ----
__global__ __launch_bounds__(256, 2)
void sage_mma_kernel(const float* __restrict__ adj)
{
    extern __shared__ float sm[];

    const int tid  = threadIdx.x;
    const int lane = tid & 31, warp = tid >> 5;
    const int wm = warp >> 1, wn = warp & 1;    // warp tile: rows 32*wm, cols 32*wn
    const int rb   = blockIdx.x >> 2;
    const int kspl = blockIdx.x & 3;
    const int row0 = rb * RM;
    const int kbase = kspl * KRANGE;

    // loader mappings
    const int rA = tid >> 1, hA = tid & 1;      // A: row rA (0..127), 32 floats at 32*hA
    const int rB = tid >> 2, qB = tid & 3;      // B: n-row rB (0..63), 16 floats at 16*qB

    const float*    aP = adj + (size_t)(row0 + rA) * NN + kbase + 32 * hA;
    const uint32_t* bP = g_featT + (size_t)rB * NN + kbase + 16 * qB;

    const uint32_t aDst = s2u(&sm[rA * SA + 32 * hA]);
    const uint32_t bDst = s2u(&sm[128 * SA + rB * SA + 16 * qB]);
    const uint32_t STGB = STG * 4;

    // ldmatrix base addresses (stage 0)
    const int mi = lane >> 3, ri = lane & 7;
    const uint32_t aAddr0 = s2u(&sm[(32 * wm + (mi & 1) * 8 + ri) * SA + (mi >> 1) * 4]);
    const uint32_t aAddr1 = aAddr0 + 16 * SA * 4;
    const uint32_t bAddr0 = s2u(&sm[128 * SA + (32 * wn + (mi >> 1) * 8 + ri) * SA + (mi & 1) * 4]);
    const uint32_t bAddr1 = bAddr0 + 16 * SA * 4;

    float acc[2][4][4] = {};
    float accR[2][4] = {};                      // rowsum accumulators (ones-MMA)
    const uint32_t ONE = 0x3f800000u;

    // stage copy: 8x16B of A + 4x16B of B per thread
    auto copy_stage = [&](int t) {
        const uint32_t off = (uint32_t)(t & 1) * STGB;
        const float*    as = aP + (size_t)t * KT;
        const uint32_t* bs = bP + t * KT;
        #pragma unroll
        for (int j = 0; j < 8; j++) cpasync16(aDst + off + j * 16, as + 4 * j);
        #pragma unroll
        for (int j = 0; j < 4; j++) cpasync16(bDst + off + j * 16, bs + 4 * j);
    };

    copy_stage(0); cp_commit();
    copy_stage(1); cp_commit();

    for (int t = 0; t < NT; t++) {
        const uint32_t off = (uint32_t)(t & 1) * STGB;
        cp_wait1();              // stage t landed (per-thread)
        __syncthreads();         // landed for everyone

        const uint32_t aA0 = aAddr0 + off, aA1 = aAddr1 + off;
        const uint32_t bA0 = bAddr0 + off, bA1 = bAddr1 + off;

        #pragma unroll
        for (int ks = 0; ks < 8; ks++) {
            uint32_t a0[4], a1[4], b0[4], b1[4];
            ldsm4(a0, aA0 + ks * 32);
            ldsm4(a1, aA1 + ks * 32);
            ldsm4(b0, bA0 + ks * 32);
            ldsm4(b1, bA1 + ks * 32);
            mma_tf32(acc[0][0], a0, b0[0], b0[1]);
            mma_tf32(acc[0][1], a0, b0[2], b0[3]);
            mma_tf32(acc[0][2], a0, b1[0], b1[1]);
            mma_tf32(acc[0][3], a0, b1[2], b1[3]);
            mma_tf32(acc[1][0], a1, b0[0], b0[1]);
            mma_tf32(acc[1][1], a1, b0[2], b0[3]);
            mma_tf32(acc[1][2], a1, b1[0], b1[1]);
            mma_tf32(acc[1][3], a1, b1[2], b1[3]);
            mma_tf32(accR[0], a0, ONE, ONE);    // rowsum: adj @ ones
            mma_tf32(accR[1], a1, ONE, ONE);
        }
        __syncthreads();         // everyone done reading buffer (t&1)

        if (t + 2 < NT) copy_stage(t + 2);
        cp_commit();             // unconditional: keeps group accounting uniform
    }

    // ---- partial rowsums from ones-MMA accumulators ----
    // accR[ab][0] = rowsum(row 32wm+16ab+lane/4); accR[ab][2] = that row + 8
    if (wn == 0 && (lane & 3) == 0) {
        const int g = lane >> 2;
        #pragma unroll
        for (int ab = 0; ab < 2; ab++) {
            const int rr = 32 * wm + 16 * ab + g;
            g_rs[kspl][row0 + rr]     = accR[ab][0];
            g_rs[kspl][row0 + rr + 8] = accR[ab][2];
        }
    }

    // ---- partial neigh sums -> g_pn[kspl] ----
    {
        const int g = lane >> 2, c2 = 2 * (lane & 3);
        float* pb = &g_pn[kspl][row0][0];
        #pragma unroll
        for (int ab = 0; ab < 2; ab++) {
            #pragma unroll
            for (int nb = 0; nb < 4; nb++) {
                const int rr = 32 * wm + 16 * ab + g;
                const int cc = 32 * wn + 8 * nb + c2;
                float2 lo = make_float2(acc[ab][nb][0], acc[ab][nb][1]);
                float2 hi = make_float2(acc[ab][nb][2], acc[ab][nb][3]);
                *(float2*)(pb + (size_t)rr * FF + cc)       = lo;
                *(float2*)(pb + (size_t)(rr + 8) * FF + cc) = hi;
            }
        }
    }
}

// ---- combine: out = feat@W1^T + ((sum_s pn_s)/deg)@W2^T   (exact fp32) ----
__global__ __launch_bounds__(256)
void combine_kernel(const float* __restrict__ feat,
                    const float* __restrict__ W,
                    float* __restrict__ out)
{
    __shared__ float WsmT[128][SA];   // [k][o]

    const int tid = threadIdx.x;
    const int r = blockIdx.x * 64 + (tid >> 2);
    const int q = tid & 3;            // outputs 16q..16q+15

    {
        const int o = tid >> 2, kq = tid & 3;
        const float* wp = W + (size_t)o * 128 + 32 * kq;
        #pragma unroll
        for (int j = 0; j < 32; j++)
            WsmT[32 * kq + j][o] = wp[j];
    }
    __syncthreads();

    const float inv = 1.0f / (g_rs[0][r] + g_rs[1][r] + g_rs[2][r] + g_rs[3][r] + 1.0f);

    const float4* f4 = (const float4*)(feat + (size_t)r * FF);
    const float4* p0 = (const float4*)&g_pn[0][r][0];
    const float4* p1 = (const float4*)&g_pn[1][r][0];
    const float4* p2 = (const float4*)&g_pn[2][r][0];
    const float4* p3 = (const float4*)&g_pn[3][r][0];

    float acc[16] = {};
    #pragma unroll 4
    for (int k4 = 0; k4 < 16; k4++) {
        float4 f = f4[k4];
        float4 s0 = p0[k4], s1 = p1[k4], s2 = p2[k4], s3 = p3[k4];
        float4 an4;
        an4.x = (s0.x + s1.x + s2.x + s3.x) * inv;
        an4.y = (s0.y + s1.y + s2.y + s3.y) * inv;
        an4.z = (s0.z + s1.z + s2.z + s3.z) * inv;
        an4.w = (s0.w + s1.w + s2.w + s3.w) * inv;
        const float af[4] = {f.x, f.y, f.z, f.w};
        const float an[4] = {an4.x, an4.y, an4.z, an4.w};
        #pragma unroll
        for (int e = 0; e < 4; e++) {
            const int k = 4 * k4 + e;
            #pragma unroll
            for (int i = 0; i < 4; i++) {
                float4 w1 = *(const float4*)&WsmT[k][16 * q + 4 * i];
                float4 w2 = *(const float4*)&WsmT[64 + k][16 * q + 4 * i];
                acc[4 * i + 0] = fmaf(af[e], w1.x, fmaf(an[e], w2.x, acc[4 * i + 0]));
                acc[4 * i + 1] = fmaf(af[e], w1.y, fmaf(an[e], w2.y, acc[4 * i + 1]));
                acc[4 * i + 2] = fmaf(af[e], w1.z, fmaf(an[e], w2.z, acc[4 * i + 2]));
                acc[4 * i + 3] = fmaf(af[e], w1.w, fmaf(an[e], w2.w, acc[4 * i + 3]));
            }
        }
    }

    float* op = out + (size_t)r * FF + 16 * q;
    #pragma unroll
    for (int i = 0; i < 4; i++)
        *(float4*)(op + 4 * i) = make_float4(acc[4 * i + 0], acc[4 * i + 1],
                                             acc[4 * i + 2], acc[4 * i + 3]);
}

extern "C" void kernel_launch(void* const* d_in, const int* in_sizes, int n_in,
                              void* d_out, int out_size)
{
    const float* adj  = (const float*)d_in[0];   // [8192, 8192]
    const float* feat = (const float*)d_in[1];   // [8192, 64]
    const float* W    = (const float*)d_in[2];   // [64, 128]
    float* out        = (float*)d_out;           // [8192, 64]

    cudaFuncSetAttribute(sage_mma_kernel,
                         cudaFuncAttributeMaxDynamicSharedMemorySize, SMEM_BYTES);
    prep_featT<<<NN / 64, 256>>>(feat);
    sage_mma_kernel<<<(NN / RM) * KSPLIT, 256, SMEM_BYTES>>>(adj);
    combine_kernel<<<NN / 64, 256>>>(feat, W, out);
}

// round 17
// speedup vs baseline: 2.5358x; 1.2988x over previous
#include <cuda_runtime.h>
#include <cstdint>

#define NN 8192
#define FF 64
#define RM 128                 // rows per CTA
#define KT 32                  // k-tile
#define KSPLIT 4
#define KRANGE (NN / KSPLIT)   // 2048
#define NT (KRANGE / KT)       // 64 tiles per CTA
#define SA 36                  // smem row stride (floats): 32 + 4 pad
#define STG (192 * SA)         // floats per stage (A 128*SA + B 64*SA)
#define NSTAGE 4

#define SMEM_BYTES (NSTAGE * STG * 4)   // 110592 B

__device__ uint32_t g_featT[FF * NN];        // feat^T, tf32-RN bits (2MB)
__device__ float    g_pn[KSPLIT][NN][FF];    // partial neigh sums   (8MB)
__device__ float    g_rs[KSPLIT][NN];        // partial rowsums

static __device__ __forceinline__ uint32_t tf32b(float x) {
    uint32_t r; asm("cvt.rna.tf32.f32 %0, %1;" : "=r"(r) : "f"(x)); return r;
}
static __device__ __forceinline__ uint32_t s2u(const void* p) {
    uint32_t a;
    asm("{ .reg .u64 t; cvta.to.shared.u64 t, %1; cvt.u32.u64 %0, t; }" : "=r"(a) : "l"(p));
    return a;
}
static __device__ __forceinline__ void cpasync16(uint32_t dst, const void* src) {
    asm volatile("cp.async.cg.shared.global [%0], [%1], 16;"
                 :: "r"(dst), "l"(src) : "memory");
}
static __device__ __forceinline__ void cp_commit() {
    asm volatile("cp.async.commit_group;" ::: "memory");
}
static __device__ __forceinline__ void cp_wait2() {
    asm volatile("cp.async.wait_group 2;" ::: "memory");
}
static __device__ __forceinline__ void ldsm4(uint32_t* f, uint32_t addr) {
    asm volatile("ldmatrix.sync.aligned.m8n8.x4.shared.b16 {%0,%1,%2,%3}, [%4];"
                 : "=r"(f[0]), "=r"(f[1]), "=r"(f[2]), "=r"(f[3]) : "r"(addr));
}
static __device__ __forceinline__ void mma_tf32(float* c, const uint32_t* a,
                                                uint32_t b0, uint32_t b1) {
    asm volatile(
        "mma.sync.aligned.m16n8k8.row.col.f32.tf32.tf32.f32 "
        "{%0,%1,%2,%3}, {%4,%5,%6,%7}, {%8,%9}, {%0,%1,%2,%3};"
        : "+f"(c[0]), "+f"(c[1]), "+f"(c[2]), "+f"(c[3])
        : "r"(a[0]), "r"(a[1]), "r"(a[2]), "r"(a[3]), "r"(b0), "r"(b1));
}

// ---- prep: featT[n][k] = tf32_rn(feat[k][n]) ----
__global__ __launch_bounds__(256)
void prep_featT(const float* __restrict__ feat)
{
    __shared__ float t[64][65];
    const int k0 = blockIdx.x * 64;
    const int tid = threadIdx.x;
    const int r = tid >> 2, q = tid & 3;

    const float* fp = feat + (size_t)(k0 + r) * FF + 16 * q;
    #pragma unroll
    for (int j = 0; j < 4; j++) {
        float4 v = *(const float4*)(fp + 4 * j);
        t[r][16 * q + 4 * j + 0] = v.x;
        t[r][16 * q + 4 * j + 1] = v.y;
        t[r][16 * q + 4 * j + 2] = v.z;
        t[r][16 * q + 4 * j + 3] = v.w;
    }
    __syncthreads();

    uint32_t* dst = g_featT + (size_t)r * NN + k0 + 16 * q;
    #pragma unroll
    for (int j = 0; j < 4; j++) {
        uint4 c;
        c.x = tf32b(t[16 * q + 4 * j + 0][r]);
        c.y = tf32b(t[16 * q + 4 * j + 1][r]);
        c.z = tf32b(t[16 * q + 4 * j + 2][r]);
        c.w = tf32b(t[16 * q + 4 * j + 3][r]);
        *(uint4*)(dst + 4 * j) = c;
    }
}

// ---- main kernel: 4-stage cp.async pipeline, ONE sync per tile ----
__global__ __launch_bounds__(256, 2)
void sage_mma_kernel(const float* __restrict__ adj)
{
    extern __shared__ float sm[];

    const int tid  = threadIdx.x;
    const int lane = tid & 31, warp = tid >> 5;
    const int wm = warp >> 1, wn = warp & 1;    // warp tile: rows 32*wm, cols 32*wn
    const int rb   = blockIdx.x >> 2;
    const int kspl = blockIdx.x & 3;
    const int row0 = rb * RM;
    const int kbase = kspl * KRANGE;

    // loader mappings (KT=32)
    const int rA = tid >> 1, hA = tid & 1;      // A: row rA (0..127), 16 floats at 16*hA
    const int rB = tid >> 2, qB = tid & 3;      // B: n-row rB (0..63), 8 floats at 8*qB

    const float*    aP = adj + (size_t)(row0 + rA) * NN + kbase + 16 * hA;
    const uint32_t* bP = g_featT + (size_t)rB * NN + kbase + 8 * qB;

    const uint32_t aDst = s2u(&sm[rA * SA + 16 * hA]);
    const uint32_t bDst = s2u(&sm[128 * SA + rB * SA + 8 * qB]);
    const uint32_t STGB = STG * 4;

    // ldmatrix base addresses (stage 0)
    const int mi = lane >> 3, ri = lane & 7;
    const uint32_t aAddr0 = s2u(&sm[(32 * wm + (mi & 1) * 8 + ri) * SA + (mi >> 1) * 4]);
    const uint32_t aAddr1 = aAddr0 + 16 * SA * 4;
    const uint32_t bAddr0 = s2u(&sm[128 * SA + (32 * wn + (mi >> 1) * 8 + ri) * SA + (mi & 1) * 4]);
    const uint32_t bAddr1 = bAddr0 + 16 * SA * 4;

    float acc[2][4][4] = {};
    float accR[2][4] = {};                      // rowsum accumulators (ones-MMA)
    const uint32_t ONE = 0x3f800000u;

    // stage copy: 4x16B of A + 2x16B of B per thread
    auto copy_stage = [&](int t) {
        const uint32_t off = (uint32_t)(t & 3) * STGB;
        const float*    as = aP + (size_t)t * KT;
        const uint32_t* bs = bP + t * KT;
        #pragma unroll
        for (int j = 0; j < 4; j++) cpasync16(aDst + off + j * 16, as + 4 * j);
        #pragma unroll
        for (int j = 0; j < 2; j++) cpasync16(bDst + off + j * 16, bs + 4 * j);
    };

    copy_stage(0); cp_commit();
    copy_stage(1); cp_commit();
    copy_stage(2); cp_commit();

    for (int t = 0; t < NT; t++) {
        const uint32_t off = (uint32_t)(t & 3) * STGB;
        cp_wait2();              // stage t landed (2 younger groups may be pending)
        __syncthreads();         // landed for everyone; buffer (t+3)&3 free to overwrite

        const uint32_t aA0 = aAddr0 + off, aA1 = aAddr1 + off;
        const uint32_t bA0 = bAddr0 + off, bA1 = bAddr1 + off;

        #pragma unroll
        for (int ks = 0; ks < 4; ks++) {
            uint32_t a0[4], a1[4], b0[4], b1[4];
            ldsm4(a0, aA0 + ks * 32);
            ldsm4(a1, aA1 + ks * 32);
            ldsm4(b0, bA0 + ks * 32);
            ldsm4(b1, bA1 + ks * 32);
            mma_tf32(acc[0][0], a0, b0[0], b0[1]);
            mma_tf32(acc[0][1], a0, b0[2], b0[3]);
            mma_tf32(acc[0][2], a0, b1[0], b1[1]);
            mma_tf32(acc[0][3], a0, b1[2], b1[3]);
            mma_tf32(acc[1][0], a1, b0[0], b0[1]);
            mma_tf32(acc[1][1], a1, b0[2], b0[3]);
            mma_tf32(acc[1][2], a1, b1[0], b1[1]);
            mma_tf32(acc[1][3], a1, b1[2], b1[3]);
            mma_tf32(accR[0], a0, ONE, ONE);    // rowsum: adj @ ones
            mma_tf32(accR[1], a1, ONE, ONE);
        }

        if (t + 3 < NT) copy_stage(t + 3);
        cp_commit();             // unconditional: uniform group accounting
    }

    // ---- partial rowsums from ones-MMA accumulators ----
    if (wn == 0 && (lane & 3) == 0) {
        const int g = lane >> 2;
        #pragma unroll
        for (int ab = 0; ab < 2; ab++) {
            const int rr = 32 * wm + 16 * ab + g;
            g_rs[kspl][row0 + rr]     = accR[ab][0];
            g_rs[kspl][row0 + rr + 8] = accR[ab][2];
        }
    }

    // ---- partial neigh sums -> g_pn[kspl] ----
    {
        const int g = lane >> 2, c2 = 2 * (lane & 3);
        float* pb = &g_pn[kspl][row0][0];
        #pragma unroll
        for (int ab = 0; ab < 2; ab++) {
            #pragma unroll
            for (int nb = 0; nb < 4; nb++) {
                const int rr = 32 * wm + 16 * ab + g;
                const int cc = 32 * wn + 8 * nb + c2;
                float2 lo = make_float2(acc[ab][nb][0], acc[ab][nb][1]);
                float2 hi = make_float2(acc[ab][nb][2], acc[ab][nb][3]);
                *(float2*)(pb + (size_t)rr * FF + cc)       = lo;
                *(float2*)(pb + (size_t)(rr + 8) * FF + cc) = hi;
            }
        }
    }
}

// ---- combine: out = feat@W1^T + ((sum_s pn_s)/deg)@W2^T   (exact fp32) ----
__global__ __launch_bounds__(256)
void combine_kernel(const float* __restrict__ feat,
                    const float* __restrict__ W,
                    float* __restrict__ out)
{
    __shared__ float WsmT[128][68];   // [k][o]

    const int tid = threadIdx.x;
    const int r = blockIdx.x * 64 + (tid >> 2);
    const int q = tid & 3;            // outputs 16q..16q+15

    {
        const int o = tid >> 2, kq = tid & 3;
        const float* wp = W + (size_t)o * 128 + 32 * kq;
        #pragma unroll
        for (int j = 0; j < 32; j++)
            WsmT[32 * kq + j][o] = wp[j];
    }
    __syncthreads();

    const float inv = 1.0f / (g_rs[0][r] + g_rs[1][r] + g_rs[2][r] + g_rs[3][r] + 1.0f);

    const float4* f4 = (const float4*)(feat + (size_t)r * FF);
    const float4* p0 = (const float4*)&g_pn[0][r][0];
    const float4* p1 = (const float4*)&g_pn[1][r][0];
    const float4* p2 = (const float4*)&g_pn[2][r][0];
    const float4* p3 = (const float4*)&g_pn[3][r][0];

    float acc[16] = {};
    #pragma unroll 4
    for (int k4 = 0; k4 < 16; k4++) {
        float4 f = f4[k4];
        float4 s0 = p0[k4], s1 = p1[k4], s2 = p2[k4], s3 = p3[k4];
        float4 an4;
        an4.x = (s0.x + s1.x + s2.x + s3.x) * inv;
        an4.y = (s0.y + s1.y + s2.y + s3.y) * inv;
        an4.z = (s0.z + s1.z + s2.z + s3.z) * inv;
        an4.w = (s0.w + s1.w + s2.w + s3.w) * inv;
        const float af[4] = {f.x, f.y, f.z, f.w};
        const float an[4] = {an4.x, an4.y, an4.z, an4.w};
        #pragma unroll
        for (int e = 0; e < 4; e++) {
            const int k = 4 * k4 + e;
            #pragma unroll
            for (int i = 0; i < 4; i++) {
                float4 w1 = *(const float4*)&WsmT[k][16 * q + 4 * i];
                float4 w2 = *(const float4*)&WsmT[64 + k][16 * q + 4 * i];
                acc[4 * i + 0] = fmaf(af[e], w1.x, fmaf(an[e], w2.x, acc[4 * i + 0]));
                acc[4 * i + 1] = fmaf(af[e], w1.y, fmaf(an[e], w2.y, acc[4 * i + 1]));
                acc[4 * i + 2] = fmaf(af[e], w1.z, fmaf(an[e], w2.z, acc[4 * i + 2]));
                acc[4 * i + 3] = fmaf(af[e], w1.w, fmaf(an[e], w2.w, acc[4 * i + 3]));
            }
        }
    }

    float* op = out + (size_t)r * FF + 16 * q;
    #pragma unroll
    for (int i = 0; i < 4; i++)
        *(float4*)(op + 4 * i) = make_float4(acc[4 * i + 0], acc[4 * i + 1],
                                             acc[4 * i + 2], acc[4 * i + 3]);
}

extern "C" void kernel_launch(void* const* d_in, const int* in_sizes, int n_in,
                              void* d_out, int out_size)
{
    const float* adj  = (const float*)d_in[0];   // [8192, 8192]
    const float* feat = (const float*)d_in[1];   // [8192, 64]
    const float* W    = (const float*)d_in[2];   // [64, 128]
    float* out        = (float*)d_out;           // [8192, 64]

    cudaFuncSetAttribute(sage_mma_kernel,
                         cudaFuncAttributeMaxDynamicSharedMemorySize, SMEM_BYTES);
    prep_featT<<<NN / 64, 256>>>(feat);
    sage_mma_kernel<<<(NN / RM) * KSPLIT, 256, SMEM_BYTES>>>(adj);
    combine_kernel<<<NN / 64, 256>>>(feat, W, out);
}